// round 1
// baseline (speedup 1.0000x reference)
#include <cuda_runtime.h>
#include <math.h>

// Problem shapes (fixed by the dataset):
//   features: [B=2, C=512, H=50, W=64] float32
//   roiss   : [B=2, N=128, 4]          float32  (x1,y1,x2,y2 pixel coords)
//   out     : [B, N, C]                float32
#define BB 2
#define CC 512
#define HH 50
#define WW 64
#define NN 128

__global__ __launch_bounds__(CC) void roipool_kernel(
    const float* __restrict__ feat,
    const float* __restrict__ rois,
    float* __restrict__ out)
{
    const int bn = blockIdx.x;           // 0 .. B*N-1
    const int b  = bn / NN;
    const int c  = threadIdx.x;          // one thread per channel

    // --- box computation (exactly mirrors the jax reference) ---
    const float4 r = reinterpret_cast<const float4*>(rois)[bn];
    // norm = roi / [1024, 800, 1024, 800]  (IEEE f32 div, round-nearest)
    const float nx1 = __fmul_rn(__fdiv_rn(r.x, 1024.0f), (float)WW);
    const float ny1 = __fmul_rn(__fdiv_rn(r.y,  800.0f), (float)HH);
    const float nx2 = __fmul_rn(__fdiv_rn(r.z, 1024.0f), (float)WW);
    const float ny2 = __fmul_rn(__fdiv_rn(r.w,  800.0f), (float)HH);

    int x1 = max((int)floorf(nx1), 0);
    int y1 = max((int)floorf(ny1), 0);
    int x2 = max((int)ceilf(nx2), 0);
    int y2 = max((int)ceilf(ny2), 0);

    // degenerate-box fixes from the reference
    if (x1 == 0 && x2 == 0) x2 = 1;
    if (y1 == 0 && y2 == 0) y2 = 1;
    if (x1 >= WW) x1 = WW - 1;
    if (y1 >= HH) y1 = HH - 1;

    // half-open membership over the image grid => clamp upper to H/W
    const int xe = min(x2, WW);
    const int ye = min(y2, HH);

    const float* base = feat + ((size_t)(b * CC + c)) * (HH * WW);

    float m = -INFINITY;
    for (int y = y1; y < ye; ++y) {
        const float* row = base + y * WW;
        // Window width is <= 7 for this dataset (box width <= 84px -> <= 5.25
        // feature cols + floor/ceil slack). 8 predicated loads, fully
        // unrolled, give MLP=8 per row.
        #pragma unroll
        for (int i = 0; i < 8; ++i) {
            const int x = x1 + i;
            if (x < xe) m = fmaxf(m, __ldg(row + x));
        }
        // safety net for wider windows (never taken with these shapes)
        for (int x = x1 + 8; x < xe; ++x) m = fmaxf(m, __ldg(row + x));
    }

    out[(size_t)bn * CC + c] = m;
}

extern "C" void kernel_launch(void* const* d_in, const int* in_sizes, int n_in,
                              void* d_out, int out_size)
{
    const float* feat = (const float*)d_in[0];   // [B, C, H, W]
    const float* rois = (const float*)d_in[1];   // [B, N, 4]
    float* out        = (float*)d_out;           // [B, N, C]
    (void)in_sizes; (void)n_in; (void)out_size;

    roipool_kernel<<<BB * NN, CC>>>(feat, rois, out);
}

// round 2
// speedup vs baseline: 1.6416x; 1.6416x over previous
#include <cuda_runtime.h>
#include <math.h>

// Shapes (fixed by dataset):
//   features: [B=2, C=512, H=50, W=64] float32
//   roiss   : [B=2, N=128, 4]          float32
//   out     : [B, N, C]                float32
#define BB 2
#define CC 512
#define HH 50
#define WW 64
#define NN 128
#define HWSZ (HH * WW)   // 3200

// Scratch: features transposed to [B, H, W, C]  (13.1 MB)
__device__ float g_tfeat[BB * HWSZ * CC];

// ---------------------------------------------------------------------------
// Kernel 1: transpose [B, C, HW] -> [B, HW, C] with 32x32 smem tiles.
// Reads coalesced along HW, writes coalesced along C.
// ---------------------------------------------------------------------------
__global__ __launch_bounds__(256) void transpose_kernel(
    const float* __restrict__ feat)
{
    __shared__ float tile[32][33];

    const int b   = blockIdx.z;
    const int c0  = blockIdx.y * 32;   // C tile origin (C=512 -> 16 tiles)
    const int hw0 = blockIdx.x * 32;   // HW tile origin (HW=3200 -> 100 tiles)
    const int tx  = threadIdx.x;       // 0..31
    const int ty  = threadIdx.y;       // 0..7

    const float* src = feat + (size_t)b * CC * HWSZ;
    float* dst       = g_tfeat + (size_t)b * HWSZ * CC;

    // Load: src[c0+ty+j][hw0+tx], coalesced in hw (tx)
    #pragma unroll
    for (int j = 0; j < 32; j += 8) {
        tile[ty + j][tx] = src[(size_t)(c0 + ty + j) * HWSZ + (hw0 + tx)];
    }
    __syncthreads();

    // Store: dst[hw0+ty+j][c0+tx], coalesced in c (tx)
    #pragma unroll
    for (int j = 0; j < 32; j += 8) {
        dst[(size_t)(hw0 + ty + j) * CC + (c0 + tx)] = tile[tx][ty + j];
    }
}

// ---------------------------------------------------------------------------
// Kernel 2: ROI max-pool from [B, H, W, C]. One block per (b, n), one thread
// per channel. Each window-position read is 512*4B contiguous across block.
// ---------------------------------------------------------------------------
__global__ __launch_bounds__(CC) void pool_kernel(
    const float* __restrict__ rois,
    float* __restrict__ out)
{
    const int bn = blockIdx.x;       // 0 .. B*N-1
    const int b  = bn / NN;
    const int c  = threadIdx.x;      // channel

    // --- box computation (byte-identical to jax reference path) ---
    const float4 r = reinterpret_cast<const float4*>(rois)[bn];
    const float nx1 = __fmul_rn(__fdiv_rn(r.x, 1024.0f), (float)WW);
    const float ny1 = __fmul_rn(__fdiv_rn(r.y,  800.0f), (float)HH);
    const float nx2 = __fmul_rn(__fdiv_rn(r.z, 1024.0f), (float)WW);
    const float ny2 = __fmul_rn(__fdiv_rn(r.w,  800.0f), (float)HH);

    int x1 = max((int)floorf(nx1), 0);
    int y1 = max((int)floorf(ny1), 0);
    int x2 = max((int)ceilf(nx2), 0);
    int y2 = max((int)ceilf(ny2), 0);

    if (x1 == 0 && x2 == 0) x2 = 1;
    if (y1 == 0 && y2 == 0) y2 = 1;
    if (x1 >= WW) x1 = WW - 1;
    if (y1 >= HH) y1 = HH - 1;

    const int xe = min(x2, WW);
    const int ye = min(y2, HH);

    const float* base = g_tfeat + (size_t)b * HWSZ * CC + c;

    float m = -INFINITY;
    for (int y = y1; y < ye; ++y) {
        const float* row = base + (size_t)(y * WW) * CC;
        // window width <= 7 for this dataset; 8 predicated loads -> MLP=8
        #pragma unroll
        for (int i = 0; i < 8; ++i) {
            const int x = x1 + i;
            if (x < xe) m = fmaxf(m, __ldg(row + (size_t)x * CC));
        }
        for (int x = x1 + 8; x < xe; ++x)   // safety, never taken here
            m = fmaxf(m, __ldg(row + (size_t)x * CC));
    }

    out[(size_t)bn * CC + c] = m;
}

extern "C" void kernel_launch(void* const* d_in, const int* in_sizes, int n_in,
                              void* d_out, int out_size)
{
    const float* feat = (const float*)d_in[0];   // [B, C, H, W]
    const float* rois = (const float*)d_in[1];   // [B, N, 4]
    float* out        = (float*)d_out;           // [B, N, C]
    (void)in_sizes; (void)n_in; (void)out_size;

    dim3 tgrid(HWSZ / 32, CC / 32, BB);          // 100 x 16 x 2
    dim3 tblock(32, 8);
    transpose_kernel<<<tgrid, tblock>>>(feat);

    pool_kernel<<<BB * NN, CC>>>(rois, out);
}